// round 13
// baseline (speedup 1.0000x reference)
#include <cuda_runtime.h>
#include <cuda_fp16.h>
#include <math.h>
#include <stdint.h>

#define BB 16
#define NN 1024
#define DD 256
#define L2E 1.4426950408889634f
#define LN2F 0.6931471805599453f

// fp16 arrays: logK * log2(e) (log2 domain) — the ONLY K storage (64 MB).
static __device__ __half d_logKh [BB*NN*NN];  // 32 MB row-major
static __device__ __half d_logKTh[BB*NN*NN];  // 32 MB transposed
// potentials in LOG2 domain
static __device__ float  d_f[BB*NN];
static __device__ float  d_g[BB*NN];
static __device__ __half d_fh[BB*NN];
static __device__ __half d_gh[BB*NN];
static __device__ float d_inx[BB*NN];
static __device__ float d_iny[BB*NN];
static __device__ float d_r[BB*NN];
static __device__ float d_c[BB*NN];
static __device__ float d_xg[BB*DD];
static __device__ float d_yg[BB*DD];
static __device__ float d_Lmain[BB];
static __device__ float d_LbX[BB];
static __device__ float d_LbY[BB];
static __device__ float d_loss[BB];

__device__ __forceinline__ float warpMax(float v){
  #pragma unroll
  for (int o=16;o>0;o>>=1) v = fmaxf(v, __shfl_xor_sync(0xffffffffu, v, o));
  return v;
}
__device__ __forceinline__ float warpSum(float v){
  #pragma unroll
  for (int o=16;o>0;o>>=1) v += __shfl_xor_sync(0xffffffffu, v, o);
  return v;
}
__device__ __forceinline__ float blockSum256(float v, float* sm){
  __syncthreads();
  v = warpSum(v);
  int w = threadIdx.x>>5, l = threadIdx.x&31;
  if (l==0) sm[w]=v;
  __syncthreads();
  if (w==0){
    float t = (l<8)? sm[l] : 0.0f;
    t = warpSum(t);
    if (l==0) sm[0]=t;
  }
  __syncthreads();
  return sm[0];
}

__device__ __forceinline__ void fma2(unsigned long long& d, unsigned long long a, unsigned long long b){
  asm("fma.rn.f32x2 %0, %1, %2, %0;" : "+l"(d) : "l"(a), "l"(b));
}
__device__ __forceinline__ void unpack2(unsigned long long p, float& lo, float& hi){
  asm("mov.b64 {%0,%1}, %2;" : "=f"(lo), "=f"(hi) : "l"(p));
}
__device__ __forceinline__ unsigned long long pack2(float lo, float hi){
  unsigned long long r;
  asm("mov.b64 %0, {%1,%2};" : "=l"(r) : "f"(lo), "f"(hi));
  return r;
}

__device__ __forceinline__ unsigned long long mk_policy(){
  unsigned long long p;
  asm("createpolicy.fractional.L2::evict_last.b64 %0, 1.0;" : "=l"(p));
  return p;
}
__device__ __forceinline__ uint4 ld_el4(const __half* p, unsigned long long pol){
  uint4 v;
  asm volatile("ld.global.nc.L2::cache_hint.v4.u32 {%0,%1,%2,%3}, [%4], %5;"
    : "=r"(v.x),"=r"(v.y),"=r"(v.z),"=r"(v.w) : "l"(p), "l"(pol));
  return v;
}
__device__ __forceinline__ uint4 ld_cg4(const __half* p){
  uint4 v;
  asm volatile("ld.global.cg.v4.u32 {%0,%1,%2,%3}, [%4];"
    : "=r"(v.x),"=r"(v.y),"=r"(v.z),"=r"(v.w) : "l"(p));
  return v;
}

// ---------------- init: zero accumulators (graph replays!) -------------------
__global__ void k_init(){
  int t = blockIdx.x*256 + threadIdx.x;
  for (int i=t; i<BB*NN; i += gridDim.x*256){
    d_g[i] = 0.0f;
    d_gh[i] = __ushort_as_half((unsigned short)0);
  }
  for (int i=t; i<BB*DD; i += gridDim.x*256){ d_xg[i]=0.0f; d_yg[i]=0.0f; }
  if (t < BB){ d_Lmain[t]=0.0f; d_LbX[t]=0.0f; d_LbY[t]=0.0f; }
}

// ---------------- inverse row norms (one warp per row) -----------------------
__global__ void __launch_bounds__(256) k_norms(const float* __restrict__ X, const float* __restrict__ Y){
  int warp = threadIdx.x>>5, lane = threadIdx.x&31;
  int row = blockIdx.x*8 + warp;
  const float* src = blockIdx.y ? Y : X;
  float* dst = blockIdx.y ? d_iny : d_inx;
  const float* p = src + (size_t)row*DD;
  float4 a = *(const float4*)(p + lane*4);
  float4 c = *(const float4*)(p + 128 + lane*4);
  float ss = a.x*a.x+a.y*a.y+a.z*a.z+a.w*a.w
           + c.x*c.x+c.y*c.y+c.z*c.z+c.w*c.w;
  ss = warpSum(ss);
  if (lane==0) dst[row] = 1.0f / fmaxf(sqrtf(ss), 1e-12f);
}

// ------- S = Xn Yn^T -> logKh (fp16 log2-domain, row + transposed) -----------
__global__ void __launch_bounds__(256) k_gemm(const float* __restrict__ X, const float* __restrict__ Y){
  __shared__ __align__(16) unsigned long long As2[32][68];
  __shared__ __align__(16) float Bs[32][68];
  int b = blockIdx.z;
  int i0 = blockIdx.y*64, j0 = blockIdx.x*64;
  int tid = threadIdx.x;
  const float* Xp = X + ((size_t)(b*NN + i0))*DD;
  const float* Yp = Y + ((size_t)(b*NN + j0))*DD;
  int lrow = tid>>3, lk4 = (tid&7)*4;
  int tx = tid&15, ty = tid>>4;
  unsigned long long acc2[4][2];
  #pragma unroll
  for (int u=0;u<4;u++){ acc2[u][0]=0ull; acc2[u][1]=0ull; }

  for (int kc=0; kc<DD; kc+=32){
    #pragma unroll
    for (int h=0;h<2;h++){
      int r = lrow + h*32;
      float4 a = *(const float4*)(Xp + (size_t)r*DD + kc + lk4);
      *(float2*)&As2[lk4+0][r] = make_float2(a.x,a.x);
      *(float2*)&As2[lk4+1][r] = make_float2(a.y,a.y);
      *(float2*)&As2[lk4+2][r] = make_float2(a.z,a.z);
      *(float2*)&As2[lk4+3][r] = make_float2(a.w,a.w);
      float4 bv = *(const float4*)(Yp + (size_t)r*DD + kc + lk4);
      Bs[lk4+0][r]=bv.x; Bs[lk4+1][r]=bv.y; Bs[lk4+2][r]=bv.z; Bs[lk4+3][r]=bv.w;
    }
    __syncthreads();
    #pragma unroll
    for (int k=0;k<32;k++){
      unsigned long long a0 = As2[k][ty*4+0];
      unsigned long long a1 = As2[k][ty*4+1];
      unsigned long long a2 = As2[k][ty*4+2];
      unsigned long long a3 = As2[k][ty*4+3];
      unsigned long long b0 = *(const unsigned long long*)&Bs[k][tx*4];
      unsigned long long b1 = *(const unsigned long long*)&Bs[k][tx*4+2];
      fma2(acc2[0][0],a0,b0); fma2(acc2[0][1],a0,b1);
      fma2(acc2[1][0],a1,b0); fma2(acc2[1][1],a1,b1);
      fma2(acc2[2][0],a2,b0); fma2(acc2[2][1],a2,b1);
      fma2(acc2[3][0],a3,b0); fma2(acc2[3][1],a3,b1);
    }
    __syncthreads();
  }
  float acc[4][4];
  #pragma unroll
  for (int u=0;u<4;u++){
    unpack2(acc2[u][0], acc[u][0], acc[u][1]);
    unpack2(acc2[u][1], acc[u][2], acc[u][3]);
  }
  float inx[4], iny[4];
  #pragma unroll
  for (int u=0;u<4;u++){
    inx[u] = d_inx[b*NN + i0 + ty*4 + u];
    iny[u] = d_iny[b*NN + j0 + tx*4 + u];
  }
  float o[4][4];
  #pragma unroll
  for (int u=0;u<4;u++){
    int i = i0 + ty*4 + u;
    #pragma unroll
    for (int w=0;w<4;w++){
      int j = j0 + tx*4 + w;
      float S = acc[u][w]*inx[u]*iny[w];
      float q = fmaxf(1.0f - S, 0.0f);
      float pj = fabsf((float)(i-j))*(1.0f/1023.0f);
      o[u][w] = (-100.0f*q - 0.2f*pj)*L2E;    // logK * log2e
    }
    size_t off = ((size_t)(b*NN+i))*NN + j0 + tx*4;
    __half2* hp = (__half2*)(d_logKh + off);
    hp[0] = __floats2half2_rn(o[u][0], o[u][1]);
    hp[1] = __floats2half2_rn(o[u][2], o[u][3]);
  }
  // ---- transposed fp16 writes via smem staging ----
  float* tb = (float*)As2;
  __syncthreads();
  #pragma unroll
  for (int u=0;u<4;u++)
    #pragma unroll
    for (int w=0;w<4;w++)
      tb[(tx*4+w)*65 + ty*4+u] = o[u][w];
  __syncthreads();
  int jl = tid>>2, seg = tid&3;
  size_t toff = ((size_t)(b*NN + j0 + jl))*NN + i0 + seg*16;
  #pragma unroll
  for (int h=0;h<4;h++){
    float v0 = tb[jl*65 + seg*16 + h*4 + 0];
    float v1 = tb[jl*65 + seg*16 + h*4 + 1];
    float v2 = tb[jl*65 + seg*16 + h*4 + 2];
    float v3 = tb[jl*65 + seg*16 + h*4 + 3];
    __half2* hp = (__half2*)(d_logKTh + toff + h*4);
    hp[0] = __floats2half2_rn(v0, v1);
    hp[1] = __floats2half2_rn(v2, v3);
  }
}

// ---- one row of the sinkhorn LSE (log2 domain, packed half2) ----------------
__device__ __forceinline__ void lse_row(const __half* Mh, const __half* ph,
                                        float* outp, __half* outh,
                                        int row, int lane, unsigned long long pol){
  int b = row >> 10;
  const __half* mk = Mh + (size_t)row*NN;
  const __half* gp = ph + (size_t)b*NN;
  __half2 x[16];
  #pragma unroll
  for (int w=0;w<4;w++){
    int e = (w*32 + lane)*8;
    uint4 kv = ld_el4(mk + e, pol);
    uint4 gv = ld_cg4(gp + e);
    x[w*4+0] = __hadd2(*(__half2*)&kv.x, *(__half2*)&gv.x);
    x[w*4+1] = __hadd2(*(__half2*)&kv.y, *(__half2*)&gv.y);
    x[w*4+2] = __hadd2(*(__half2*)&kv.z, *(__half2*)&gv.z);
    x[w*4+3] = __hadd2(*(__half2*)&kv.w, *(__half2*)&gv.w);
  }
  __half2 m01 = __hmax2(x[0],x[1]),   m23 = __hmax2(x[2],x[3]);
  __half2 m45 = __hmax2(x[4],x[5]),   m67 = __hmax2(x[6],x[7]);
  __half2 m89 = __hmax2(x[8],x[9]),   mab = __hmax2(x[10],x[11]);
  __half2 mcd = __hmax2(x[12],x[13]), mef = __hmax2(x[14],x[15]);
  __half2 ma = __hmax2(__hmax2(m01,m23), __hmax2(m45,m67));
  __half2 mb = __hmax2(__hmax2(m89,mab), __hmax2(mcd,mef));
  __half2 mm = __hmax2(ma, mb);
  float Ml = fmaxf(__low2float(mm), __high2float(mm));
  float Mw = warpMax(Ml);
  __half2 M2 = __float2half2_rn(Mw);
  __half2 s0 = h2exp2(__hsub2(x[0], M2));
  __half2 s1 = h2exp2(__hsub2(x[1], M2));
  __half2 s2 = h2exp2(__hsub2(x[2], M2));
  __half2 s3 = h2exp2(__hsub2(x[3], M2));
  #pragma unroll
  for (int q=4;q<16;q+=4){
    s0 = __hadd2(s0, h2exp2(__hsub2(x[q+0], M2)));
    s1 = __hadd2(s1, h2exp2(__hsub2(x[q+1], M2)));
    s2 = __hadd2(s2, h2exp2(__hsub2(x[q+2], M2)));
    s3 = __hadd2(s3, h2exp2(__hsub2(x[q+3], M2)));
  }
  float2 f0 = __half22float2(s0), f1 = __half22float2(s1);
  float2 f2 = __half22float2(s2), f3 = __half22float2(s3);
  float S = (f0.x+f0.y) + (f1.x+f1.y) + (f2.x+f2.y) + (f3.x+f3.y);
  float Sw = warpSum(S);
  if (lane==0){
    float out = -10.0f - (Mw + __log2f(Sw));
    outp[row] = out;
    outh[row] = __float2half_rn(out);
  }
}

// ---- cluster-per-batch persistent sinkhorn ----------------------------------
// 16 clusters x 16 CTAs x 512 thr. Cluster = batch: 256 warps, 4 rows/warp.
// HW cluster barrier between phases (release/acquire, ~380 cyc).
__global__ void __launch_bounds__(512) k_sinkc(){
  int b  = blockIdx.x >> 4;          // cluster id = batch
  int cr = blockIdx.x & 15;          // rank within cluster
  int wc = cr*16 + (threadIdx.x>>5); // warp 0..255 within cluster
  int lane = threadIdx.x & 31;
  int row0 = b*NN + wc*4;
  unsigned long long pol = mk_policy();
  for (int it=0; it<50; it++){
    #pragma unroll 1
    for (int rr=0; rr<4; rr++)
      lse_row(d_logKh, d_gh, d_f, d_fh, row0+rr, lane, pol);
    __threadfence();
    asm volatile("barrier.cluster.arrive.aligned;" ::: "memory");
    asm volatile("barrier.cluster.wait.aligned;"   ::: "memory");
    #pragma unroll 1
    for (int rr=0; rr<4; rr++)
      lse_row(d_logKTh, d_fh, d_g, d_gh, row0+rr, lane, pol);
    __threadfence();
    asm volatile("barrier.cluster.arrive.aligned;" ::: "memory");
    asm volatile("barrier.cluster.wait.aligned;"   ::: "memory");
  }
}

// ---- fused marginal pass: fp16 K source, f32x2 matvec -----------------------
template<int MAIN>
__global__ void __launch_bounds__(256) k_pass(const float* __restrict__ X, const float* __restrict__ Y){
  const __half* Mh = MAIN ? d_logKh : d_logKTh;
  const float* rpp = MAIN ? d_f : d_g;
  const float* cpp = MAIN ? d_g : d_f;
  const float* V   = MAIN ? Y : X;
  const float* W   = MAIN ? X : Y;
  float* sum_out   = MAIN ? d_r : d_c;
  float* Lb_out    = MAIN ? d_LbX : d_LbY;

  __shared__ float csh[NN];
  __shared__ __align__(16) float Tsh[64][36];
  __shared__ float ssh[32];
  __shared__ float rsh[32];
  __shared__ float red[32];
  int b = blockIdx.y, i0 = blockIdx.x*32;
  int tid = threadIdx.x;
  int lane = tid&31, wp = tid>>5;
  unsigned long long pol = mk_policy();
  for (int j=tid; j<NN; j+=256) csh[j] = cpp[b*NN + j];
  if (tid<32){ ssh[tid]=0.0f; rsh[tid]=rpp[b*NN + i0 + tid]; }
  __syncthreads();
  unsigned long long acc2[16];
  #pragma unroll
  for (int r=0;r<16;r++) acc2[r]=0ull;
  float lmain = 0.0f;
  const __half* lkb = Mh + ((size_t)(b*NN + i0))*NN;
  const float* Vp  = V + ((size_t)b*NN)*DD + tid;

  for (int kc=0; kc<NN; kc+=64){
    float fv = rsh[lane];
    uint4 kv = ld_el4(lkb + (size_t)lane*NN + kc + wp*8, pol);
    float2 p0 = __half22float2(*(__half2*)&kv.x);
    float2 p1 = __half22float2(*(__half2*)&kv.y);
    float2 p2 = __half22float2(*(__half2*)&kv.z);
    float2 p3 = __half22float2(*(__half2*)&kv.w);
    float lk2[8] = {p0.x,p0.y,p1.x,p1.y,p2.x,p2.y,p3.x,p3.y};
    float rpart = 0.0f;
    #pragma unroll
    for (int u=0;u<8;u++){
      int j = kc + wp*8 + u;
      float t = exp2f(lk2[u] + fv + csh[j]);
      Tsh[wp*8+u][lane] = t;
      rpart += t;
      if (MAIN){
        float pj = fabsf((float)(i0 + lane - j))*(1.0f/1023.0f);
        lmain = fmaf(t, (-lk2[u]*LN2F - 0.2f*pj)*0.1f, lmain);
      }
    }
    atomicAdd(&ssh[lane], rpart);
    __syncthreads();
    #pragma unroll 2
    for (int k=0;k<64;k++){
      float yv = Vp[(size_t)(kc+k)*DD];
      unsigned long long yv2 = pack2(yv, yv);
      const ulonglong2* trow = (const ulonglong2*)&Tsh[k][0];
      #pragma unroll
      for (int q=0;q<8;q++){
        ulonglong2 tv = trow[q];
        fma2(acc2[2*q+0], tv.x, yv2);
        fma2(acc2[2*q+1], tv.y, yv2);
      }
    }
    __syncthreads();
  }
  if (MAIN){
    float lm = blockSum256(lmain, red);
    if (tid==0) atomicAdd(&d_Lmain[b], lm);
  }
  if (tid<32) sum_out[b*NN + i0 + tid] = ssh[tid];
  float acc[32];
  #pragma unroll
  for (int r=0;r<16;r++) unpack2(acc2[r], acc[2*r], acc[2*r+1]);
  float lb = 0.0f;
  const float* Wp = W + ((size_t)(b*NN + i0))*DD + tid;
  #pragma unroll
  for (int r=0;r<32;r++){
    float yb = acc[r] / (ssh[r] + 1e-8f);
    float diff = Wp[(size_t)r*DD] - yb;
    lb = fmaf(diff, diff, lb);
  }
  lb = blockSum256(lb, red);
  if (tid==0) atomicAdd(Lb_out + b, lb);
}

// ------------ global token: partial weighted sums (parallel) -----------------
__global__ void __launch_bounds__(256) k_gpart(const float* __restrict__ X, const float* __restrict__ Y){
  int b = blockIdx.y, i0 = blockIdx.x*128;
  int d = threadIdx.x;
  const float* Xp = X + ((size_t)(b*NN + i0))*DD + d;
  const float* Yp = Y + ((size_t)(b*NN + i0))*DD + d;
  const float* rp = d_r + b*NN + i0;
  const float* cp = d_c + b*NN + i0;
  float xg=0.0f, yg=0.0f;
  #pragma unroll 4
  for (int i=0;i<128;i++){
    xg = fmaf(Xp[(size_t)i*DD], rp[i], xg);
    yg = fmaf(Yp[(size_t)i*DD], cp[i], yg);
  }
  atomicAdd(&d_xg[b*DD+d], xg);
  atomicAdd(&d_yg[b*DD+d], yg);
}

// ------------ global cosine + per-batch loss combine -------------------------
__global__ void __launch_bounds__(256) k_gfin(){
  __shared__ float red[32];
  int b = blockIdx.x, d = threadIdx.x;
  float srp = 0.0f, scp = 0.0f;
  #pragma unroll
  for (int q=0;q<4;q++){
    srp += d_r[b*NN + q*256 + d];
    scp += d_c[b*NN + q*256 + d];
  }
  float sr = blockSum256(srp, red);
  float sc = blockSum256(scp, red);
  float xg = d_xg[b*DD+d] / (sr + 1e-8f);
  float yg = d_yg[b*DD+d] / (sc + 1e-8f);
  float ssx = blockSum256(xg*xg, red);
  float ssy = blockSum256(yg*yg, red);
  float ix = 1.0f / fmaxf(sqrtf(ssx), 1e-12f);
  float iy = 1.0f / fmaxf(sqrtf(ssy), 1e-12f);
  float dot = blockSum256((xg*ix)*(yg*iy), red);
  if (d==0){
    float lcos = 1.0f - dot;
    float lbary = (d_LbX[b] + d_LbY[b]) * (1.0f/((float)NN*(float)DD));
    d_loss[b] = d_Lmain[b] + 0.5f*lbary + 0.2f*lcos;
  }
}

__global__ void k_final(float* out){
  int t = threadIdx.x;
  float v = (t < BB) ? d_loss[t] : 0.0f;
  v = warpSum(v);
  if (t==0) out[0] = v * (1.0f/(float)BB);
}

extern "C" void kernel_launch(void* const* d_in, const int* in_sizes, int n_in,
                              void* d_out, int out_size) {
  const float* X = (const float*)d_in[0];   // eeg_embedding  (B,N,D)
  const float* Y = (const float*)d_in[1];   // text_embedding (B,N,D)
  float* out = (float*)d_out;
  (void)in_sizes; (void)n_in; (void)out_size;

  k_init<<<64, 256>>>();
  k_norms<<<dim3(BB*NN/8, 2), 256>>>(X, Y);
  k_gemm<<<dim3(NN/64, NN/64, BB), 256>>>(X, Y);

  // one launch: all 50 sinkhorn iterations, one 16-CTA cluster per batch
  cudaFuncSetAttribute((const void*)k_sinkc,
                       cudaFuncAttributeNonPortableClusterSizeAllowed, 1);
  cudaLaunchConfig_t cfg = {};
  cfg.gridDim  = dim3(BB*16, 1, 1);    // 256 CTAs
  cfg.blockDim = dim3(512, 1, 1);
  cudaLaunchAttribute attrs[1];
  attrs[0].id = cudaLaunchAttributeClusterDimension;
  attrs[0].val.clusterDim = {16, 1, 1};
  cfg.attrs = attrs;
  cfg.numAttrs = 1;
  cudaLaunchKernelEx(&cfg, k_sinkc);

  k_pass<1><<<dim3(NN/32, BB), 256>>>(X, Y);   // rows: r, T@Y, L_main, LbX
  k_pass<0><<<dim3(NN/32, BB), 256>>>(X, Y);   // cols: c, T^T@X, LbY
  k_gpart<<<dim3(NN/128, BB), 256>>>(X, Y);
  k_gfin<<<BB, 256>>>();
  k_final<<<1, 32>>>(out);
}

// round 15
// speedup vs baseline: 1.1265x; 1.1265x over previous
#include <cuda_runtime.h>
#include <cuda_fp16.h>
#include <math.h>
#include <stdint.h>

#define BB 16
#define NN 1024
#define DD 256
#define L2E 1.4426950408889634f
#define LN2F 0.6931471805599453f

// fp16 arrays: logK * log2(e) (log2 domain) — the ONLY K storage (64 MB).
static __device__ __half d_logKh [BB*NN*NN];  // 32 MB row-major
static __device__ __half d_logKTh[BB*NN*NN];  // 32 MB transposed
// potentials in LOG2 domain
static __device__ float  d_f[BB*NN];
static __device__ float  d_g[BB*NN];
static __device__ __half d_fh[BB*NN];
static __device__ __half d_gh[BB*NN];
static __device__ float d_inx[BB*NN];
static __device__ float d_iny[BB*NN];
static __device__ float d_r[BB*NN];
static __device__ float d_c[BB*NN];
static __device__ float d_xg[BB*DD];
static __device__ float d_yg[BB*DD];
static __device__ float d_Lmain[BB];
static __device__ float d_LbX[BB];
static __device__ float d_LbY[BB];
static __device__ float d_loss[BB];

__device__ __forceinline__ float warpMax(float v){
  #pragma unroll
  for (int o=16;o>0;o>>=1) v = fmaxf(v, __shfl_xor_sync(0xffffffffu, v, o));
  return v;
}
__device__ __forceinline__ float warpSum(float v){
  #pragma unroll
  for (int o=16;o>0;o>>=1) v += __shfl_xor_sync(0xffffffffu, v, o);
  return v;
}
__device__ __forceinline__ float blockSum256(float v, float* sm){
  __syncthreads();
  v = warpSum(v);
  int w = threadIdx.x>>5, l = threadIdx.x&31;
  if (l==0) sm[w]=v;
  __syncthreads();
  if (w==0){
    float t = (l<8)? sm[l] : 0.0f;
    t = warpSum(t);
    if (l==0) sm[0]=t;
  }
  __syncthreads();
  return sm[0];
}

__device__ __forceinline__ void fma2(unsigned long long& d, unsigned long long a, unsigned long long b){
  asm("fma.rn.f32x2 %0, %1, %2, %0;" : "+l"(d) : "l"(a), "l"(b));
}
__device__ __forceinline__ void unpack2(unsigned long long p, float& lo, float& hi){
  asm("mov.b64 {%0,%1}, %2;" : "=f"(lo), "=f"(hi) : "l"(p));
}
__device__ __forceinline__ unsigned long long pack2(float lo, float hi){
  unsigned long long r;
  asm("mov.b64 %0, {%1,%2};" : "=l"(r) : "f"(lo), "f"(hi));
  return r;
}
__device__ __forceinline__ unsigned long long mk_policy(){
  unsigned long long p;
  asm("createpolicy.fractional.L2::evict_last.b64 %0, 1.0;" : "=l"(p));
  return p;
}
__device__ __forceinline__ uint4 ld_el4(const __half* p, unsigned long long pol){
  uint4 v;
  asm volatile("ld.global.nc.L2::cache_hint.v4.u32 {%0,%1,%2,%3}, [%4], %5;"
    : "=r"(v.x),"=r"(v.y),"=r"(v.z),"=r"(v.w) : "l"(p), "l"(pol));
  return v;
}
__device__ __forceinline__ uint32_t s2u(const void* p){
  uint32_t a;
  asm("{ .reg .u64 t; cvta.to.shared.u64 t, %1; cvt.u32.u64 %0, t; }" : "=r"(a) : "l"(p));
  return a;
}

// ---------------- init: zero accumulators (graph replays!) -------------------
__global__ void k_init(){
  int t = blockIdx.x*256 + threadIdx.x;
  for (int i=t; i<BB*NN; i += gridDim.x*256){
    d_g[i] = 0.0f;
    d_gh[i] = __ushort_as_half((unsigned short)0);
  }
  for (int i=t; i<BB*DD; i += gridDim.x*256){ d_xg[i]=0.0f; d_yg[i]=0.0f; }
  if (t < BB){ d_Lmain[t]=0.0f; d_LbX[t]=0.0f; d_LbY[t]=0.0f; }
}

// ---------------- inverse row norms (one warp per row) -----------------------
__global__ void __launch_bounds__(256) k_norms(const float* __restrict__ X, const float* __restrict__ Y){
  int warp = threadIdx.x>>5, lane = threadIdx.x&31;
  int row = blockIdx.x*8 + warp;
  const float* src = blockIdx.y ? Y : X;
  float* dst = blockIdx.y ? d_iny : d_inx;
  const float* p = src + (size_t)row*DD;
  float4 a = *(const float4*)(p + lane*4);
  float4 c = *(const float4*)(p + 128 + lane*4);
  float ss = a.x*a.x+a.y*a.y+a.z*a.z+a.w*a.w
           + c.x*c.x+c.y*c.y+c.z*c.z+c.w*c.w;
  ss = warpSum(ss);
  if (lane==0) dst[row] = 1.0f / fmaxf(sqrtf(ss), 1e-12f);
}

// ------- S = Xn Yn^T -> logKh (fp16 log2-domain, row + transposed) -----------
__global__ void __launch_bounds__(256) k_gemm(const float* __restrict__ X, const float* __restrict__ Y){
  __shared__ __align__(16) unsigned long long As2[32][68];
  __shared__ __align__(16) float Bs[32][68];
  int b = blockIdx.z;
  int i0 = blockIdx.y*64, j0 = blockIdx.x*64;
  int tid = threadIdx.x;
  const float* Xp = X + ((size_t)(b*NN + i0))*DD;
  const float* Yp = Y + ((size_t)(b*NN + j0))*DD;
  int lrow = tid>>3, lk4 = (tid&7)*4;
  int tx = tid&15, ty = tid>>4;
  unsigned long long acc2[4][2];
  #pragma unroll
  for (int u=0;u<4;u++){ acc2[u][0]=0ull; acc2[u][1]=0ull; }

  for (int kc=0; kc<DD; kc+=32){
    #pragma unroll
    for (int h=0;h<2;h++){
      int r = lrow + h*32;
      float4 a = *(const float4*)(Xp + (size_t)r*DD + kc + lk4);
      *(float2*)&As2[lk4+0][r] = make_float2(a.x,a.x);
      *(float2*)&As2[lk4+1][r] = make_float2(a.y,a.y);
      *(float2*)&As2[lk4+2][r] = make_float2(a.z,a.z);
      *(float2*)&As2[lk4+3][r] = make_float2(a.w,a.w);
      float4 bv = *(const float4*)(Yp + (size_t)r*DD + kc + lk4);
      Bs[lk4+0][r]=bv.x; Bs[lk4+1][r]=bv.y; Bs[lk4+2][r]=bv.z; Bs[lk4+3][r]=bv.w;
    }
    __syncthreads();
    #pragma unroll
    for (int k=0;k<32;k++){
      unsigned long long a0 = As2[k][ty*4+0];
      unsigned long long a1 = As2[k][ty*4+1];
      unsigned long long a2 = As2[k][ty*4+2];
      unsigned long long a3 = As2[k][ty*4+3];
      unsigned long long b0 = *(const unsigned long long*)&Bs[k][tx*4];
      unsigned long long b1 = *(const unsigned long long*)&Bs[k][tx*4+2];
      fma2(acc2[0][0],a0,b0); fma2(acc2[0][1],a0,b1);
      fma2(acc2[1][0],a1,b0); fma2(acc2[1][1],a1,b1);
      fma2(acc2[2][0],a2,b0); fma2(acc2[2][1],a2,b1);
      fma2(acc2[3][0],a3,b0); fma2(acc2[3][1],a3,b1);
    }
    __syncthreads();
  }
  float acc[4][4];
  #pragma unroll
  for (int u=0;u<4;u++){
    unpack2(acc2[u][0], acc[u][0], acc[u][1]);
    unpack2(acc2[u][1], acc[u][2], acc[u][3]);
  }
  float inx[4], iny[4];
  #pragma unroll
  for (int u=0;u<4;u++){
    inx[u] = d_inx[b*NN + i0 + ty*4 + u];
    iny[u] = d_iny[b*NN + j0 + tx*4 + u];
  }
  float o[4][4];
  #pragma unroll
  for (int u=0;u<4;u++){
    int i = i0 + ty*4 + u;
    #pragma unroll
    for (int w=0;w<4;w++){
      int j = j0 + tx*4 + w;
      float S = acc[u][w]*inx[u]*iny[w];
      float q = fmaxf(1.0f - S, 0.0f);
      float pj = fabsf((float)(i-j))*(1.0f/1023.0f);
      o[u][w] = (-100.0f*q - 0.2f*pj)*L2E;    // logK * log2e
    }
    size_t off = ((size_t)(b*NN+i))*NN + j0 + tx*4;
    __half2* hp = (__half2*)(d_logKh + off);
    hp[0] = __floats2half2_rn(o[u][0], o[u][1]);
    hp[1] = __floats2half2_rn(o[u][2], o[u][3]);
  }
  // ---- transposed fp16 writes via smem staging ----
  float* tb = (float*)As2;
  __syncthreads();
  #pragma unroll
  for (int u=0;u<4;u++)
    #pragma unroll
    for (int w=0;w<4;w++)
      tb[(tx*4+w)*65 + ty*4+u] = o[u][w];
  __syncthreads();
  int jl = tid>>2, seg = tid&3;
  size_t toff = ((size_t)(b*NN + j0 + jl))*NN + i0 + seg*16;
  #pragma unroll
  for (int h=0;h<4;h++){
    float v0 = tb[jl*65 + seg*16 + h*4 + 0];
    float v1 = tb[jl*65 + seg*16 + h*4 + 1];
    float v2 = tb[jl*65 + seg*16 + h*4 + 2];
    float v3 = tb[jl*65 + seg*16 + h*4 + 3];
    __half2* hp = (__half2*)(d_logKTh + toff + h*4);
    hp[0] = __floats2half2_rn(v0, v1);
    hp[1] = __floats2half2_rn(v2, v3);
  }
}

// ---- sinkhorn half-iteration: TMA bulk-copy K rows + potentials to smem -----
// CTA = 8 consecutive rows (16 KB contiguous). One cp.async.bulk each for K
// and the 2 KB potential vector; mbarrier completion; packed-half2 LSE.
template<int MODE>
__global__ void __launch_bounds__(256) k_lse(){
  __shared__ __align__(128) __half sK[8*NN];            // 16 KB
  __shared__ __align__(128) __half sG[NN];              // 2 KB
  __shared__ __align__(8)  unsigned long long mbar[1];
  int warp = threadIdx.x>>5, lane = threadIdx.x&31;
  int row0 = blockIdx.x*8;
  int b = row0 >> 10;
  const __half* Mh  = MODE ? d_logKTh : d_logKh;
  const __half* ph  = MODE ? d_fh : d_gh;
  float* outp       = MODE ? d_g : d_f;
  __half* outh      = MODE ? d_gh : d_fh;
  uint32_t mb = s2u(mbar);
  if (threadIdx.x == 0)
    asm volatile("mbarrier.init.shared.b64 [%0], 1;" :: "r"(mb) : "memory");
  __syncthreads();
  if (threadIdx.x == 0){
    asm volatile("mbarrier.arrive.expect_tx.shared.b64 _, [%0], %1;"
      :: "r"(mb), "r"((unsigned)(8*NN*2 + NN*2)) : "memory");
    asm volatile("cp.async.bulk.shared::cta.global.mbarrier::complete_tx::bytes [%0], [%1], %2, [%3];"
      :: "r"(s2u(sK)), "l"(Mh + (size_t)row0*NN), "r"((unsigned)(8*NN*2)), "r"(mb) : "memory");
    asm volatile("cp.async.bulk.shared::cta.global.mbarrier::complete_tx::bytes [%0], [%1], %2, [%3];"
      :: "r"(s2u(sG)), "l"(ph + (size_t)b*NN), "r"((unsigned)(NN*2)), "r"(mb) : "memory");
  }
  {
    uint32_t done = 0;
    while (!done)
      asm volatile("{\n\t.reg .pred p;\n\t"
        "mbarrier.try_wait.parity.acquire.cta.shared::cta.b64 p, [%1], 0, 0x989680;\n\t"
        "selp.b32 %0, 1, 0, p;\n\t}"
        : "=r"(done) : "r"(mb) : "memory");
  }
  const uint4* mk = (const uint4*)(sK + warp*NN);
  const uint4* gk = (const uint4*)sG;
  __half2 x[16];
  #pragma unroll
  for (int w=0;w<4;w++){
    int idx = w*32 + lane;
    uint4 kv = mk[idx];
    uint4 gv = gk[idx];
    x[w*4+0] = __hadd2(*(__half2*)&kv.x, *(__half2*)&gv.x);
    x[w*4+1] = __hadd2(*(__half2*)&kv.y, *(__half2*)&gv.y);
    x[w*4+2] = __hadd2(*(__half2*)&kv.z, *(__half2*)&gv.z);
    x[w*4+3] = __hadd2(*(__half2*)&kv.w, *(__half2*)&gv.w);
  }
  __half2 m01 = __hmax2(x[0],x[1]),   m23 = __hmax2(x[2],x[3]);
  __half2 m45 = __hmax2(x[4],x[5]),   m67 = __hmax2(x[6],x[7]);
  __half2 m89 = __hmax2(x[8],x[9]),   mab = __hmax2(x[10],x[11]);
  __half2 mcd = __hmax2(x[12],x[13]), mef = __hmax2(x[14],x[15]);
  __half2 ma = __hmax2(__hmax2(m01,m23), __hmax2(m45,m67));
  __half2 mb2 = __hmax2(__hmax2(m89,mab), __hmax2(mcd,mef));
  __half2 mm = __hmax2(ma, mb2);
  float Ml = fmaxf(__low2float(mm), __high2float(mm));
  float Mw = warpMax(Ml);
  __half2 M2 = __float2half2_rn(Mw);
  __half2 s0 = h2exp2(__hsub2(x[0], M2));
  __half2 s1 = h2exp2(__hsub2(x[1], M2));
  __half2 s2 = h2exp2(__hsub2(x[2], M2));
  __half2 s3 = h2exp2(__hsub2(x[3], M2));
  #pragma unroll
  for (int q=4;q<16;q+=4){
    s0 = __hadd2(s0, h2exp2(__hsub2(x[q+0], M2)));
    s1 = __hadd2(s1, h2exp2(__hsub2(x[q+1], M2)));
    s2 = __hadd2(s2, h2exp2(__hsub2(x[q+2], M2)));
    s3 = __hadd2(s3, h2exp2(__hsub2(x[q+3], M2)));
  }
  float2 f0 = __half22float2(s0), f1 = __half22float2(s1);
  float2 f2 = __half22float2(s2), f3 = __half22float2(s3);
  float S = (f0.x+f0.y) + (f1.x+f1.y) + (f2.x+f2.y) + (f3.x+f3.y);
  float Sw = warpSum(S);
  if (lane==0){
    float out = -10.0f - (Mw + __log2f(Sw));
    outp[row0 + warp] = out;
    outh[row0 + warp] = __float2half_rn(out);
  }
}

// ---- fused marginal pass: fp16 K source, f32x2 matvec -----------------------
template<int MAIN>
__global__ void __launch_bounds__(256) k_pass(const float* __restrict__ X, const float* __restrict__ Y){
  const __half* Mh = MAIN ? d_logKh : d_logKTh;
  const float* rpp = MAIN ? d_f : d_g;
  const float* cpp = MAIN ? d_g : d_f;
  const float* V   = MAIN ? Y : X;
  const float* W   = MAIN ? X : Y;
  float* sum_out   = MAIN ? d_r : d_c;
  float* Lb_out    = MAIN ? d_LbX : d_LbY;

  __shared__ float csh[NN];
  __shared__ __align__(16) float Tsh[64][36];
  __shared__ float ssh[32];
  __shared__ float rsh[32];
  __shared__ float red[32];
  int b = blockIdx.y, i0 = blockIdx.x*32;
  int tid = threadIdx.x;
  int lane = tid&31, wp = tid>>5;
  unsigned long long pol = mk_policy();
  for (int j=tid; j<NN; j+=256) csh[j] = cpp[b*NN + j];
  if (tid<32){ ssh[tid]=0.0f; rsh[tid]=rpp[b*NN + i0 + tid]; }
  __syncthreads();
  unsigned long long acc2[16];
  #pragma unroll
  for (int r=0;r<16;r++) acc2[r]=0ull;
  float lmain = 0.0f;
  const __half* lkb = Mh + ((size_t)(b*NN + i0))*NN;
  const float* Vp  = V + ((size_t)b*NN)*DD + tid;

  for (int kc=0; kc<NN; kc+=64){
    float fv = rsh[lane];
    uint4 kv = ld_el4(lkb + (size_t)lane*NN + kc + wp*8, pol);
    float2 p0 = __half22float2(*(__half2*)&kv.x);
    float2 p1 = __half22float2(*(__half2*)&kv.y);
    float2 p2 = __half22float2(*(__half2*)&kv.z);
    float2 p3 = __half22float2(*(__half2*)&kv.w);
    float lk2[8] = {p0.x,p0.y,p1.x,p1.y,p2.x,p2.y,p3.x,p3.y};
    float rpart = 0.0f;
    #pragma unroll
    for (int u=0;u<8;u++){
      int j = kc + wp*8 + u;
      float t = exp2f(lk2[u] + fv + csh[j]);
      Tsh[wp*8+u][lane] = t;
      rpart += t;
      if (MAIN){
        float pj = fabsf((float)(i0 + lane - j))*(1.0f/1023.0f);
        lmain = fmaf(t, (-lk2[u]*LN2F - 0.2f*pj)*0.1f, lmain);
      }
    }
    atomicAdd(&ssh[lane], rpart);
    __syncthreads();
    #pragma unroll 2
    for (int k=0;k<64;k++){
      float yv = Vp[(size_t)(kc+k)*DD];
      unsigned long long yv2 = pack2(yv, yv);
      const ulonglong2* trow = (const ulonglong2*)&Tsh[k][0];
      #pragma unroll
      for (int q=0;q<8;q++){
        ulonglong2 tv = trow[q];
        fma2(acc2[2*q+0], tv.x, yv2);
        fma2(acc2[2*q+1], tv.y, yv2);
      }
    }
    __syncthreads();
  }
  if (MAIN){
    float lm = blockSum256(lmain, red);
    if (tid==0) atomicAdd(&d_Lmain[b], lm);
  }
  if (tid<32) sum_out[b*NN + i0 + tid] = ssh[tid];
  float acc[32];
  #pragma unroll
  for (int r=0;r<16;r++) unpack2(acc2[r], acc[2*r], acc[2*r+1]);
  float lb = 0.0f;
  const float* Wp = W + ((size_t)(b*NN + i0))*DD + tid;
  #pragma unroll
  for (int r=0;r<32;r++){
    float yb = acc[r] / (ssh[r] + 1e-8f);
    float diff = Wp[(size_t)r*DD] - yb;
    lb = fmaf(diff, diff, lb);
  }
  lb = blockSum256(lb, red);
  if (tid==0) atomicAdd(Lb_out + b, lb);
}

// ------------ global token: partial weighted sums (parallel) -----------------
__global__ void __launch_bounds__(256) k_gpart(const float* __restrict__ X, const float* __restrict__ Y){
  int b = blockIdx.y, i0 = blockIdx.x*128;
  int d = threadIdx.x;
  const float* Xp = X + ((size_t)(b*NN + i0))*DD + d;
  const float* Yp = Y + ((size_t)(b*NN + i0))*DD + d;
  const float* rp = d_r + b*NN + i0;
  const float* cp = d_c + b*NN + i0;
  float xg=0.0f, yg=0.0f;
  #pragma unroll 4
  for (int i=0;i<128;i++){
    xg = fmaf(Xp[(size_t)i*DD], rp[i], xg);
    yg = fmaf(Yp[(size_t)i*DD], cp[i], yg);
  }
  atomicAdd(&d_xg[b*DD+d], xg);
  atomicAdd(&d_yg[b*DD+d], yg);
}

// ------------ global cosine + per-batch loss combine -------------------------
__global__ void __launch_bounds__(256) k_gfin(){
  __shared__ float red[32];
  int b = blockIdx.x, d = threadIdx.x;
  float srp = 0.0f, scp = 0.0f;
  #pragma unroll
  for (int q=0;q<4;q++){
    srp += d_r[b*NN + q*256 + d];
    scp += d_c[b*NN + q*256 + d];
  }
  float sr = blockSum256(srp, red);
  float sc = blockSum256(scp, red);
  float xg = d_xg[b*DD+d] / (sr + 1e-8f);
  float yg = d_yg[b*DD+d] / (sc + 1e-8f);
  float ssx = blockSum256(xg*xg, red);
  float ssy = blockSum256(yg*yg, red);
  float ix = 1.0f / fmaxf(sqrtf(ssx), 1e-12f);
  float iy = 1.0f / fmaxf(sqrtf(ssy), 1e-12f);
  float dot = blockSum256((xg*ix)*(yg*iy), red);
  if (d==0){
    float lcos = 1.0f - dot;
    float lbary = (d_LbX[b] + d_LbY[b]) * (1.0f/((float)NN*(float)DD));
    d_loss[b] = d_Lmain[b] + 0.5f*lbary + 0.2f*lcos;
  }
}

__global__ void k_final(float* out){
  int t = threadIdx.x;
  float v = (t < BB) ? d_loss[t] : 0.0f;
  v = warpSum(v);
  if (t==0) out[0] = v * (1.0f/(float)BB);
}

extern "C" void kernel_launch(void* const* d_in, const int* in_sizes, int n_in,
                              void* d_out, int out_size) {
  const float* X = (const float*)d_in[0];   // eeg_embedding  (B,N,D)
  const float* Y = (const float*)d_in[1];   // text_embedding (B,N,D)
  float* out = (float*)d_out;
  (void)in_sizes; (void)n_in; (void)out_size;

  k_init<<<64, 256>>>();
  k_norms<<<dim3(BB*NN/8, 2), 256>>>(X, Y);
  k_gemm<<<dim3(NN/64, NN/64, BB), 256>>>(X, Y);
  for (int it=0; it<50; it++){
    k_lse<0><<<BB*NN/8, 256>>>();   // f from Kh rows + g   (TMA bulk)
    k_lse<1><<<BB*NN/8, 256>>>();   // g from KTh rows + f  (TMA bulk)
  }
  k_pass<1><<<dim3(NN/32, BB), 256>>>(X, Y);   // rows: r, T@Y, L_main, LbX
  k_pass<0><<<dim3(NN/32, BB), 256>>>(X, Y);   // cols: c, T^T@X, LbY
  k_gpart<<<dim3(NN/128, BB), 256>>>(X, Y);
  k_gfin<<<BB, 256>>>();
  k_final<<<1, 32>>>(out);
}

// round 17
// speedup vs baseline: 1.1914x; 1.0575x over previous
#include <cuda_runtime.h>
#include <cuda_fp16.h>
#include <math.h>
#include <stdint.h>

#define BB 16
#define NN 1024
#define DD 256
#define L2E 1.4426950408889634f
#define LN2F 0.6931471805599453f

// fp16 arrays: logK * log2(e) (log2 domain) — the ONLY K storage (64 MB).
static __device__ __half d_logKh [BB*NN*NN];  // 32 MB row-major
static __device__ __half d_logKTh[BB*NN*NN];  // 32 MB transposed
// potentials in LOG2 domain
static __device__ float  d_f[BB*NN];
static __device__ float  d_g[BB*NN];
static __device__ __half d_fh[BB*NN];
static __device__ __half d_gh[BB*NN];
static __device__ float d_inx[BB*NN];
static __device__ float d_iny[BB*NN];
static __device__ float d_r[BB*NN];
static __device__ float d_c[BB*NN];
static __device__ float d_xg[BB*DD];
static __device__ float d_yg[BB*DD];
static __device__ float d_Lmain[BB];
static __device__ float d_LbX[BB];
static __device__ float d_LbY[BB];
static __device__ float d_loss[BB];

__device__ __forceinline__ float warpMax(float v){
  #pragma unroll
  for (int o=16;o>0;o>>=1) v = fmaxf(v, __shfl_xor_sync(0xffffffffu, v, o));
  return v;
}
__device__ __forceinline__ float warpSum(float v){
  #pragma unroll
  for (int o=16;o>0;o>>=1) v += __shfl_xor_sync(0xffffffffu, v, o);
  return v;
}
__device__ __forceinline__ float blockSum256(float v, float* sm){
  __syncthreads();
  v = warpSum(v);
  int w = threadIdx.x>>5, l = threadIdx.x&31;
  if (l==0) sm[w]=v;
  __syncthreads();
  if (w==0){
    float t = (l<8)? sm[l] : 0.0f;
    t = warpSum(t);
    if (l==0) sm[0]=t;
  }
  __syncthreads();
  return sm[0];
}

__device__ __forceinline__ void fma2(unsigned long long& d, unsigned long long a, unsigned long long b){
  asm("fma.rn.f32x2 %0, %1, %2, %0;" : "+l"(d) : "l"(a), "l"(b));
}
__device__ __forceinline__ void unpack2(unsigned long long p, float& lo, float& hi){
  asm("mov.b64 {%0,%1}, %2;" : "=f"(lo), "=f"(hi) : "l"(p));
}
__device__ __forceinline__ unsigned long long pack2(float lo, float hi){
  unsigned long long r;
  asm("mov.b64 %0, {%1,%2};" : "=l"(r) : "f"(lo), "f"(hi));
  return r;
}
__device__ __forceinline__ unsigned long long mk_policy(){
  unsigned long long p;
  asm("createpolicy.fractional.L2::evict_last.b64 %0, 1.0;" : "=l"(p));
  return p;
}
__device__ __forceinline__ uint4 ld_el4(const __half* p, unsigned long long pol){
  uint4 v;
  asm volatile("ld.global.nc.L2::cache_hint.v4.u32 {%0,%1,%2,%3}, [%4], %5;"
    : "=r"(v.x),"=r"(v.y),"=r"(v.z),"=r"(v.w) : "l"(p), "l"(pol));
  return v;
}

// ---------------- init: zero accumulators (graph replays!) -------------------
__global__ void k_init(){
  int t = blockIdx.x*256 + threadIdx.x;
  for (int i=t; i<BB*NN; i += gridDim.x*256){
    d_g[i] = 0.0f;
    d_gh[i] = __ushort_as_half((unsigned short)0);
  }
  for (int i=t; i<BB*DD; i += gridDim.x*256){ d_xg[i]=0.0f; d_yg[i]=0.0f; }
  if (t < BB){ d_Lmain[t]=0.0f; d_LbX[t]=0.0f; d_LbY[t]=0.0f; }
}

// ---------------- inverse row norms (one warp per row) -----------------------
__global__ void __launch_bounds__(256) k_norms(const float* __restrict__ X, const float* __restrict__ Y){
  int warp = threadIdx.x>>5, lane = threadIdx.x&31;
  int row = blockIdx.x*8 + warp;
  const float* src = blockIdx.y ? Y : X;
  float* dst = blockIdx.y ? d_iny : d_inx;
  const float* p = src + (size_t)row*DD;
  float4 a = *(const float4*)(p + lane*4);
  float4 c = *(const float4*)(p + 128 + lane*4);
  float ss = a.x*a.x+a.y*a.y+a.z*a.z+a.w*a.w
           + c.x*c.x+c.y*c.y+c.z*c.z+c.w*c.w;
  ss = warpSum(ss);
  if (lane==0) dst[row] = 1.0f / fmaxf(sqrtf(ss), 1e-12f);
}

// ------- S = Xn Yn^T -> logKh (fp16 log2-domain, row + transposed) -----------
__global__ void __launch_bounds__(256) k_gemm(const float* __restrict__ X, const float* __restrict__ Y){
  __shared__ __align__(16) unsigned long long As2[32][68];
  __shared__ __align__(16) float Bs[32][68];
  int b = blockIdx.z;
  int i0 = blockIdx.y*64, j0 = blockIdx.x*64;
  int tid = threadIdx.x;
  const float* Xp = X + ((size_t)(b*NN + i0))*DD;
  const float* Yp = Y + ((size_t)(b*NN + j0))*DD;
  int lrow = tid>>3, lk4 = (tid&7)*4;
  int tx = tid&15, ty = tid>>4;
  unsigned long long acc2[4][2];
  #pragma unroll
  for (int u=0;u<4;u++){ acc2[u][0]=0ull; acc2[u][1]=0ull; }

  for (int kc=0; kc<DD; kc+=32){
    #pragma unroll
    for (int h=0;h<2;h++){
      int r = lrow + h*32;
      float4 a = *(const float4*)(Xp + (size_t)r*DD + kc + lk4);
      *(float2*)&As2[lk4+0][r] = make_float2(a.x,a.x);
      *(float2*)&As2[lk4+1][r] = make_float2(a.y,a.y);
      *(float2*)&As2[lk4+2][r] = make_float2(a.z,a.z);
      *(float2*)&As2[lk4+3][r] = make_float2(a.w,a.w);
      float4 bv = *(const float4*)(Yp + (size_t)r*DD + kc + lk4);
      Bs[lk4+0][r]=bv.x; Bs[lk4+1][r]=bv.y; Bs[lk4+2][r]=bv.z; Bs[lk4+3][r]=bv.w;
    }
    __syncthreads();
    #pragma unroll
    for (int k=0;k<32;k++){
      unsigned long long a0 = As2[k][ty*4+0];
      unsigned long long a1 = As2[k][ty*4+1];
      unsigned long long a2 = As2[k][ty*4+2];
      unsigned long long a3 = As2[k][ty*4+3];
      unsigned long long b0 = *(const unsigned long long*)&Bs[k][tx*4];
      unsigned long long b1 = *(const unsigned long long*)&Bs[k][tx*4+2];
      fma2(acc2[0][0],a0,b0); fma2(acc2[0][1],a0,b1);
      fma2(acc2[1][0],a1,b0); fma2(acc2[1][1],a1,b1);
      fma2(acc2[2][0],a2,b0); fma2(acc2[2][1],a2,b1);
      fma2(acc2[3][0],a3,b0); fma2(acc2[3][1],a3,b1);
    }
    __syncthreads();
  }
  float acc[4][4];
  #pragma unroll
  for (int u=0;u<4;u++){
    unpack2(acc2[u][0], acc[u][0], acc[u][1]);
    unpack2(acc2[u][1], acc[u][2], acc[u][3]);
  }
  float inx[4], iny[4];
  #pragma unroll
  for (int u=0;u<4;u++){
    inx[u] = d_inx[b*NN + i0 + ty*4 + u];
    iny[u] = d_iny[b*NN + j0 + tx*4 + u];
  }
  float o[4][4];
  #pragma unroll
  for (int u=0;u<4;u++){
    int i = i0 + ty*4 + u;
    #pragma unroll
    for (int w=0;w<4;w++){
      int j = j0 + tx*4 + w;
      float S = acc[u][w]*inx[u]*iny[w];
      float q = fmaxf(1.0f - S, 0.0f);
      float pj = fabsf((float)(i-j))*(1.0f/1023.0f);
      o[u][w] = (-100.0f*q - 0.2f*pj)*L2E;    // logK * log2e
    }
    size_t off = ((size_t)(b*NN+i))*NN + j0 + tx*4;
    __half2* hp = (__half2*)(d_logKh + off);
    hp[0] = __floats2half2_rn(o[u][0], o[u][1]);
    hp[1] = __floats2half2_rn(o[u][2], o[u][3]);
  }
  // ---- transposed fp16 writes via smem staging ----
  float* tb = (float*)As2;
  __syncthreads();
  #pragma unroll
  for (int u=0;u<4;u++)
    #pragma unroll
    for (int w=0;w<4;w++)
      tb[(tx*4+w)*65 + ty*4+u] = o[u][w];
  __syncthreads();
  int jl = tid>>2, seg = tid&3;
  size_t toff = ((size_t)(b*NN + j0 + jl))*NN + i0 + seg*16;
  #pragma unroll
  for (int h=0;h<4;h++){
    float v0 = tb[jl*65 + seg*16 + h*4 + 0];
    float v1 = tb[jl*65 + seg*16 + h*4 + 1];
    float v2 = tb[jl*65 + seg*16 + h*4 + 2];
    float v3 = tb[jl*65 + seg*16 + h*4 + 3];
    __half2* hp = (__half2*)(d_logKTh + toff + h*4);
    hp[0] = __floats2half2_rn(v0, v1);
    hp[1] = __floats2half2_rn(v2, v3);
  }
}

// ---- sinkhorn half-iteration (log2 domain, packed half2, PDL prefetch) ------
// PDL=1: K rows are prefetched BEFORE griddepcontrol.wait (K is iteration-
// invariant), only the 2KB potential read is serialized on the prior phase.
template<int MODE, int PDL>
__global__ void __launch_bounds__(256) k_lse(){
  int warp = threadIdx.x>>5, lane = threadIdx.x&31;
  int row = blockIdx.x*8 + warp;
  int b = row >> 10;
  const __half* Mh  = MODE ? d_logKTh : d_logKh;
  const __half* ph  = MODE ? d_fh : d_gh;
  float* outp       = MODE ? d_g : d_f;
  __half* outh      = MODE ? d_gh : d_fh;
  const __half* mk = Mh + (size_t)row*NN;
  const uint4* gk = (const uint4*)(ph + (size_t)b*NN);
  unsigned long long pol = mk_policy();
  // prefetch K (stable across the sinkhorn loop)
  uint4 kv[4];
  #pragma unroll
  for (int w=0;w<4;w++) kv[w] = ld_el4(mk + (w*32 + lane)*8, pol);
  if (PDL) asm volatile("griddepcontrol.wait;" ::: "memory");
  __half2 x[16];
  #pragma unroll
  for (int w=0;w<4;w++){
    uint4 gv = gk[w*32 + lane];
    x[w*4+0] = __hadd2(*(__half2*)&kv[w].x, *(__half2*)&gv.x);
    x[w*4+1] = __hadd2(*(__half2*)&kv[w].y, *(__half2*)&gv.y);
    x[w*4+2] = __hadd2(*(__half2*)&kv[w].z, *(__half2*)&gv.z);
    x[w*4+3] = __hadd2(*(__half2*)&kv[w].w, *(__half2*)&gv.w);
  }
  // all inputs consumed: let the next phase launch & start its K prefetch
  asm volatile("griddepcontrol.launch_dependents;" ::: "memory");
  __half2 m01 = __hmax2(x[0],x[1]),   m23 = __hmax2(x[2],x[3]);
  __half2 m45 = __hmax2(x[4],x[5]),   m67 = __hmax2(x[6],x[7]);
  __half2 m89 = __hmax2(x[8],x[9]),   mab = __hmax2(x[10],x[11]);
  __half2 mcd = __hmax2(x[12],x[13]), mef = __hmax2(x[14],x[15]);
  __half2 ma = __hmax2(__hmax2(m01,m23), __hmax2(m45,m67));
  __half2 mb = __hmax2(__hmax2(m89,mab), __hmax2(mcd,mef));
  __half2 mm = __hmax2(ma, mb);
  float Ml = fmaxf(__low2float(mm), __high2float(mm));
  float Mw = warpMax(Ml);
  __half2 M2 = __float2half2_rn(Mw);
  __half2 s0 = h2exp2(__hsub2(x[0], M2));
  __half2 s1 = h2exp2(__hsub2(x[1], M2));
  __half2 s2 = h2exp2(__hsub2(x[2], M2));
  __half2 s3 = h2exp2(__hsub2(x[3], M2));
  #pragma unroll
  for (int q=4;q<16;q+=4){
    s0 = __hadd2(s0, h2exp2(__hsub2(x[q+0], M2)));
    s1 = __hadd2(s1, h2exp2(__hsub2(x[q+1], M2)));
    s2 = __hadd2(s2, h2exp2(__hsub2(x[q+2], M2)));
    s3 = __hadd2(s3, h2exp2(__hsub2(x[q+3], M2)));
  }
  float2 f0 = __half22float2(s0), f1 = __half22float2(s1);
  float2 f2 = __half22float2(s2), f3 = __half22float2(s3);
  float S = (f0.x+f0.y) + (f1.x+f1.y) + (f2.x+f2.y) + (f3.x+f3.y);
  float Sw = warpSum(S);
  if (lane==0){
    float out = -10.0f - (Mw + __log2f(Sw));
    outp[row] = out;
    outh[row] = __float2half_rn(out);
  }
}

// ---- fused marginal pass: fp16 K source, f32x2 matvec -----------------------
template<int MAIN>
__global__ void __launch_bounds__(256) k_pass(const float* __restrict__ X, const float* __restrict__ Y){
  const __half* Mh = MAIN ? d_logKh : d_logKTh;
  const float* rpp = MAIN ? d_f : d_g;
  const float* cpp = MAIN ? d_g : d_f;
  const float* V   = MAIN ? Y : X;
  const float* W   = MAIN ? X : Y;
  float* sum_out   = MAIN ? d_r : d_c;
  float* Lb_out    = MAIN ? d_LbX : d_LbY;

  __shared__ float csh[NN];
  __shared__ __align__(16) float Tsh[64][36];
  __shared__ float ssh[32];
  __shared__ float rsh[32];
  __shared__ float red[32];
  int b = blockIdx.y, i0 = blockIdx.x*32;
  int tid = threadIdx.x;
  int lane = tid&31, wp = tid>>5;
  unsigned long long pol = mk_policy();
  for (int j=tid; j<NN; j+=256) csh[j] = cpp[b*NN + j];
  if (tid<32){ ssh[tid]=0.0f; rsh[tid]=rpp[b*NN + i0 + tid]; }
  __syncthreads();
  unsigned long long acc2[16];
  #pragma unroll
  for (int r=0;r<16;r++) acc2[r]=0ull;
  float lmain = 0.0f;
  const __half* lkb = Mh + ((size_t)(b*NN + i0))*NN;
  const float* Vp  = V + ((size_t)b*NN)*DD + tid;

  for (int kc=0; kc<NN; kc+=64){
    float fv = rsh[lane];
    uint4 kv = ld_el4(lkb + (size_t)lane*NN + kc + wp*8, pol);
    float2 p0 = __half22float2(*(__half2*)&kv.x);
    float2 p1 = __half22float2(*(__half2*)&kv.y);
    float2 p2 = __half22float2(*(__half2*)&kv.z);
    float2 p3 = __half22float2(*(__half2*)&kv.w);
    float lk2[8] = {p0.x,p0.y,p1.x,p1.y,p2.x,p2.y,p3.x,p3.y};
    float rpart = 0.0f;
    #pragma unroll
    for (int u=0;u<8;u++){
      int j = kc + wp*8 + u;
      float t = exp2f(lk2[u] + fv + csh[j]);
      Tsh[wp*8+u][lane] = t;
      rpart += t;
      if (MAIN){
        float pj = fabsf((float)(i0 + lane - j))*(1.0f/1023.0f);
        lmain = fmaf(t, (-lk2[u]*LN2F - 0.2f*pj)*0.1f, lmain);
      }
    }
    atomicAdd(&ssh[lane], rpart);
    __syncthreads();
    #pragma unroll 2
    for (int k=0;k<64;k++){
      float yv = Vp[(size_t)(kc+k)*DD];
      unsigned long long yv2 = pack2(yv, yv);
      const ulonglong2* trow = (const ulonglong2*)&Tsh[k][0];
      #pragma unroll
      for (int q=0;q<8;q++){
        ulonglong2 tv = trow[q];
        fma2(acc2[2*q+0], tv.x, yv2);
        fma2(acc2[2*q+1], tv.y, yv2);
      }
    }
    __syncthreads();
  }
  if (MAIN){
    float lm = blockSum256(lmain, red);
    if (tid==0) atomicAdd(&d_Lmain[b], lm);
  }
  if (tid<32) sum_out[b*NN + i0 + tid] = ssh[tid];
  float acc[32];
  #pragma unroll
  for (int r=0;r<16;r++) unpack2(acc2[r], acc[2*r], acc[2*r+1]);
  float lb = 0.0f;
  const float* Wp = W + ((size_t)(b*NN + i0))*DD + tid;
  #pragma unroll
  for (int r=0;r<32;r++){
    float yb = acc[r] / (ssh[r] + 1e-8f);
    float diff = Wp[(size_t)r*DD] - yb;
    lb = fmaf(diff, diff, lb);
  }
  lb = blockSum256(lb, red);
  if (tid==0) atomicAdd(Lb_out + b, lb);
}

// ------------ global token: partial weighted sums (parallel) -----------------
__global__ void __launch_bounds__(256) k_gpart(const float* __restrict__ X, const float* __restrict__ Y){
  int b = blockIdx.y, i0 = blockIdx.x*128;
  int d = threadIdx.x;
  const float* Xp = X + ((size_t)(b*NN + i0))*DD + d;
  const float* Yp = Y + ((size_t)(b*NN + i0))*DD + d;
  const float* rp = d_r + b*NN + i0;
  const float* cp = d_c + b*NN + i0;
  float xg=0.0f, yg=0.0f;
  #pragma unroll 4
  for (int i=0;i<128;i++){
    xg = fmaf(Xp[(size_t)i*DD], rp[i], xg);
    yg = fmaf(Yp[(size_t)i*DD], cp[i], yg);
  }
  atomicAdd(&d_xg[b*DD+d], xg);
  atomicAdd(&d_yg[b*DD+d], yg);
}

// ------------ global cosine + per-batch loss combine -------------------------
__global__ void __launch_bounds__(256) k_gfin(){
  __shared__ float red[32];
  int b = blockIdx.x, d = threadIdx.x;
  float srp = 0.0f, scp = 0.0f;
  #pragma unroll
  for (int q=0;q<4;q++){
    srp += d_r[b*NN + q*256 + d];
    scp += d_c[b*NN + q*256 + d];
  }
  float sr = blockSum256(srp, red);
  float sc = blockSum256(scp, red);
  float xg = d_xg[b*DD+d] / (sr + 1e-8f);
  float yg = d_yg[b*DD+d] / (sc + 1e-8f);
  float ssx = blockSum256(xg*xg, red);
  float ssy = blockSum256(yg*yg, red);
  float ix = 1.0f / fmaxf(sqrtf(ssx), 1e-12f);
  float iy = 1.0f / fmaxf(sqrtf(ssy), 1e-12f);
  float dot = blockSum256((xg*ix)*(yg*iy), red);
  if (d==0){
    float lcos = 1.0f - dot;
    float lbary = (d_LbX[b] + d_LbY[b]) * (1.0f/((float)NN*(float)DD));
    d_loss[b] = d_Lmain[b] + 0.5f*lbary + 0.2f*lcos;
  }
}

__global__ void k_final(float* out){
  int t = threadIdx.x;
  float v = (t < BB) ? d_loss[t] : 0.0f;
  v = warpSum(v);
  if (t==0) out[0] = v * (1.0f/(float)BB);
}

extern "C" void kernel_launch(void* const* d_in, const int* in_sizes, int n_in,
                              void* d_out, int out_size) {
  const float* X = (const float*)d_in[0];   // eeg_embedding  (B,N,D)
  const float* Y = (const float*)d_in[1];   // text_embedding (B,N,D)
  float* out = (float*)d_out;
  (void)in_sizes; (void)n_in; (void)out_size;

  k_init<<<64, 256>>>();
  k_norms<<<dim3(BB*NN/8, 2), 256>>>(X, Y);
  k_gemm<<<dim3(NN/64, NN/64, BB), 256>>>(X, Y);

  // PDL launch config for the sinkhorn chain
  cudaLaunchConfig_t cfg = {};
  cfg.gridDim  = dim3(BB*NN/8, 1, 1);
  cfg.blockDim = dim3(256, 1, 1);
  cfg.stream = 0;
  cudaLaunchAttribute at[1];
  at[0].id = cudaLaunchAttributeProgrammaticStreamSerialization;
  at[0].val.programmaticStreamSerializationAllowed = 1;
  cfg.attrs = at;
  cfg.numAttrs = 1;

  // it=0 f-phase: normal launch (K prefetch must not race k_gemm)
  k_lse<0,0><<<BB*NN/8, 256>>>();
  cudaLaunchKernelEx(&cfg, k_lse<1,1>);          // it=0 g-phase
  for (int it=1; it<50; it++){
    cudaLaunchKernelEx(&cfg, k_lse<0,1>);        // f from Kh  + g
    cudaLaunchKernelEx(&cfg, k_lse<1,1>);        // g from KTh + f
  }

  k_pass<1><<<dim3(NN/32, BB), 256>>>(X, Y);   // rows: r, T@Y, L_main, LbX
  k_pass<0><<<dim3(NN/32, BB), 256>>>(X, Y);   // cols: c, T^T@X, LbY
  k_gpart<<<dim3(NN/128, BB), 256>>>(X, Y);
  k_gfin<<<BB, 256>>>();
  k_final<<<1, 32>>>(out);
}